// round 17
// baseline (speedup 1.0000x reference)
#include <cuda_runtime.h>
#include <cstdint>
#include <cstddef>

#define S_LEN   1024
#define BATCH   128
#define EDIM    256
#define HDIM    512
#define NCTA    128
#define NCTA_L0 64
#define NTHR    256
#define PA      68          // A-chunk smem pitch (floats): 68 mod 32 = 4 -> conflict free
#define PZ      36          // z smem pitch

// ---------------- persistent global staging (rewritten every launch) ----------------
__device__ __align__(16) float g_A0[2][BATCH][EDIM + HDIM];   // [xe | h0]
__device__ __align__(16) float g_A1[2][BATCH][2 * HDIM];      // [h0 | h1]
__device__ __align__(16) float g_h1f[BATCH][HDIM];            // full-precision h1
__device__ unsigned g_cnt = 0;
__device__ volatile unsigned g_gen = 0;

// ---------------- helpers ----------------
__device__ __forceinline__ float f2tf_f(float f) {
    unsigned u; asm("cvt.rna.tf32.f32 %0, %1;" : "=r"(u) : "f"(f));
    return __uint_as_float(u);
}
__device__ __forceinline__ void cp16(uint32_t saddr, const float* gptr) {
    asm volatile("cp.async.cg.shared.global [%0], [%1], 16;" :: "r"(saddr), "l"(gptr));
}
__device__ __forceinline__ void cp_commit() { asm volatile("cp.async.commit_group;"); }
__device__ __forceinline__ void cp_wait0()  { asm volatile("cp.async.wait_group 0;"); }
__device__ __forceinline__ void cp_wait1()  { asm volatile("cp.async.wait_group 1;"); }

__device__ __forceinline__ void mma8(float& d0, float& d1, float& d2, float& d3,
                                     unsigned a0, unsigned a1, unsigned a2, unsigned a3,
                                     unsigned b0, unsigned b1) {
    asm volatile(
        "mma.sync.aligned.m16n8k8.row.col.f32.tf32.tf32.f32 "
        "{%0,%1,%2,%3},{%4,%5,%6,%7},{%8,%9},{%0,%1,%2,%3};"
        : "+f"(d0), "+f"(d1), "+f"(d2), "+f"(d3)
        : "r"(a0), "r"(a1), "r"(a2), "r"(a3), "r"(b0), "r"(b1));
}

__device__ __forceinline__ float sigm(float x) { return 1.0f / (1.0f + __expf(-x)); }

// Sense-reversing grid barrier; all 128 CTAs co-resident (1 CTA/SM via smem).
__device__ __forceinline__ void gbar() {
    __syncthreads();
    if (threadIdx.x == 0) {
        unsigned gen = g_gen;
        __threadfence();
        if (atomicAdd(&g_cnt, 1u) == NCTA - 1) {
            atomicExch(&g_cnt, 0u);
            __threadfence();
            g_gen = gen + 1u;
        } else {
            while (g_gen == gen) { }
            __threadfence();
        }
    }
    __syncthreads();
}

// SMEM worst case (layer 1, NC=16):
//   Bp 2*16*1024 + A 2*128*68 + Z 128*36 + H 1024 + bias 32 = 55840 floats = 223360 B
#define SMEM_BYTES ((2 * 16 * 1024 + 2 * BATCH * PA + BATCH * PZ + BATCH * 8 + 32) * 4)

extern "C" __global__ void __launch_bounds__(NTHR, 1)
hybrid_qlstm_kernel(const int* __restrict__ x, const float* __restrict__ emb,
                    const float* __restrict__ W0, const float* __restrict__ b0,
                    const float* __restrict__ bb0, const float* __restrict__ W1,
                    const float* __restrict__ b1, const float* __restrict__ bb1,
                    const float* __restrict__ fcw, const float* __restrict__ fcb,
                    float* __restrict__ out)
{
    extern __shared__ float sm[];
    const int cta  = blockIdx.x;
    const int tid  = threadIdx.x;
    const int lane = tid & 31;
    const int warp = tid >> 5;            // 0..7, owns batch rows [16w, 16w+16)
    const int g    = lane >> 2;           // mma octet
    const int c4   = lane & 3;            // mma thread-in-group
    const bool is0 = (cta < NCTA_L0);
    const int  K   = is0 ? (EDIM + HDIM) : (2 * HDIM);   // 768 / 1024
    const int  NC  = K >> 6;                             // 12 / 16 chunks of 64
    const int  lcta = is0 ? cta : (cta - NCTA_L0);
    const int  u0   = lcta * 8;                          // hidden-unit base
    const float* Wg  = is0 ? W0 : W1;
    const float* bg  = is0 ? b0 : b1;
    const float* bbg = is0 ? bb0 : bb1;

    // fragment-packed weights: Bp0/Bp1[(ch*8 + kki)*128 + lane*4 + nt]
    float* Bp0 = sm;
    float* Bp1 = Bp0 + NC * 1024;
    float* Ab0 = Bp1 + NC * 1024;         // A chunk double buffer [128][PA]
    float* Ab1 = Ab0 + BATCH * PA;
    float* Zs  = Ab1 + BATCH * PA;        // [128][PZ] pre-activations
    float* Hs  = Zs + BATCH * PZ;         // [128][8]  fresh h
    float* Bs  = Hs + BATCH * 8;          // [32] bias (gate*8 + unit)

    // ---------------- prologue: pack W -> fragment layout (tf32) ----------------
    {
        const int total = NC * 1024;      // per plane
        for (int i = tid; i < total; i += NTHR) {
            const int nt  = i & 3;
            const int ln  = (i >> 2) & 31;
            const int kki = (i >> 7) & 7;
            const int ch  = i >> 10;
            const int gg  = ln >> 2, cc = ln & 3;
            const int col = (ch << 6) + (kki << 3) + cc;
            const size_t grow = (size_t)(nt * HDIM + u0 + gg) * K;
            Bp0[i] = f2tf_f(Wg[grow + col]);
            Bp1[i] = f2tf_f(Wg[grow + col + 4]);
        }
    }
    if (tid < 32) {
        const int grow = (tid >> 3) * HDIM + u0 + (tid & 7);
        Bs[tid] = bg[grow] + bbg[grow];
    }
    // zero initial-state regions: h0[-1] in A0[0], h1[-1] in A1[1]
    for (int i = cta * NTHR + tid; i < BATCH * HDIM; i += NCTA * NTHR) {
        const int b = i >> 9, c = i & 511;
        g_A0[0][b][EDIM + c] = 0.0f;
        g_A1[1][b][HDIM + c] = 0.0f;
    }
    // xe[0]: layer-0 CTA lcta owns embedding columns [4*lcta, 4*lcta+4)
    if (is0 && tid < BATCH) {
        const int e0 = lcta * 4;
        const int tok = x[(size_t)tid * S_LEN];
        const float4 v = *(const float4*)(emb + (size_t)tok * EDIM + e0);
        float* dst = &g_A0[0][tid][e0];
        dst[0] = f2tf_f(v.x); dst[1] = f2tf_f(v.y);
        dst[2] = f2tf_f(v.z); dst[3] = f2tf_f(v.w);
    }
    // cell state: thread owns batch b = tid>>1, units uo..uo+3
    const int cb_row = tid >> 1;
    const int uo     = (tid & 1) * 4;
    float creg[4];
#pragma unroll
    for (int u = 0; u < 4; ++u) creg[u] = 0.0f;

    gbar();

    // ---------------- main recurrence: S+1 pipelined iterations ----------------
    for (int k = 0; k <= S_LEN; ++k) {
        const int cb = k & 1, nb = cb ^ 1;
        const bool active = is0 ? (k < S_LEN) : (k >= 1);

        // gather xe[k+1] (layer-0 CTAs; overlaps with GEMM)
        if (is0 && tid < BATCH && (k + 1) < S_LEN) {
            const int e0 = lcta * 4;
            const int tok = x[(size_t)tid * S_LEN + (k + 1)];
            const float4 v = *(const float4*)(emb + (size_t)tok * EDIM + e0);
            float* dst = &g_A0[nb][tid][e0];
            dst[0] = f2tf_f(v.x); dst[1] = f2tf_f(v.y);
            dst[2] = f2tf_f(v.z); dst[3] = f2tf_f(v.w);
        }

        if (active) {
            const float* Ag = is0 ? &g_A0[cb][0][0] : &g_A1[cb][0][0];  // row stride K
            float acc[4][4];
#pragma unroll
            for (int nt = 0; nt < 4; ++nt)
#pragma unroll
                for (int r = 0; r < 4; ++r) acc[nt][r] = 0.0f;

            // prefetch chunk 0 (2048 cp16 over 256 threads)
#pragma unroll
            for (int i = 0; i < 8; ++i) {
                const int idx = tid + i * NTHR;
                const int row = idx >> 4, f4 = idx & 15;
                cp16((uint32_t)__cvta_generic_to_shared(Ab0 + row * PA + f4 * 4),
                     Ag + (size_t)row * K + f4 * 4);
            }
            cp_commit();

            for (int ch = 0; ch < NC; ++ch) {
                float* Acur = (ch & 1) ? Ab1 : Ab0;
                if (ch + 1 < NC) {
                    float* Anext = (ch & 1) ? Ab0 : Ab1;
                    const int kc = (ch + 1) << 6;
#pragma unroll
                    for (int i = 0; i < 8; ++i) {
                        const int idx = tid + i * NTHR;
                        const int row = idx >> 4, f4 = idx & 15;
                        cp16((uint32_t)__cvta_generic_to_shared(Anext + row * PA + f4 * 4),
                             Ag + (size_t)row * K + kc + f4 * 4);
                    }
                    cp_commit();
                    cp_wait1();
                } else {
                    cp_wait0();
                }
                __syncthreads();

                const float* Bc0 = Bp0 + (ch << 3) * 128;
                const float* Bc1 = Bp1 + (ch << 3) * 128;
                const float* Aw  = Acur + (warp * 16 + g) * PA + c4;
#pragma unroll
                for (int kki = 0; kki < 8; ++kki) {
                    const float4 bv0 = *(const float4*)(Bc0 + kki * 128 + lane * 4);
                    const float4 bv1 = *(const float4*)(Bc1 + kki * 128 + lane * 4);
                    const float* ap = Aw + kki * 8;
                    const unsigned a0 = __float_as_uint(ap[0]);
                    const unsigned a1 = __float_as_uint(ap[8 * PA]);
                    const unsigned a2 = __float_as_uint(ap[4]);
                    const unsigned a3 = __float_as_uint(ap[8 * PA + 4]);
                    mma8(acc[0][0], acc[0][1], acc[0][2], acc[0][3], a0, a1, a2, a3,
                         __float_as_uint(bv0.x), __float_as_uint(bv1.x));
                    mma8(acc[1][0], acc[1][1], acc[1][2], acc[1][3], a0, a1, a2, a3,
                         __float_as_uint(bv0.y), __float_as_uint(bv1.y));
                    mma8(acc[2][0], acc[2][1], acc[2][2], acc[2][3], a0, a1, a2, a3,
                         __float_as_uint(bv0.z), __float_as_uint(bv1.z));
                    mma8(acc[3][0], acc[3][1], acc[3][2], acc[3][3], a0, a1, a2, a3,
                         __float_as_uint(bv0.w), __float_as_uint(bv1.w));
                }
                __syncthreads();
            }

            // dump accumulators -> Zs  (warp owns batch rows [16w, 16w+16))
#pragma unroll
            for (int nt = 0; nt < 4; ++nt) {
                const int m = warp * 16 + g;
                const int n = nt * 8 + c4 * 2;
                *(float2*)&Zs[m * PZ + n]       = make_float2(acc[nt][0], acc[nt][1]);
                *(float2*)&Zs[(m + 8) * PZ + n] = make_float2(acc[nt][2], acc[nt][3]);
            }
            __syncthreads();

            // cell update: thread owns (b = tid>>1, units uo..uo+3)
            {
                const int b = cb_row;
#pragma unroll
                for (int u = 0; u < 4; ++u) {
                    const int uu = uo + u;
                    const float zf = Zs[b * PZ + uu]      + Bs[uu];
                    const float zi = Zs[b * PZ + 8 + uu]  + Bs[8 + uu];
                    const float zc = Zs[b * PZ + 16 + uu] + Bs[16 + uu];
                    const float zo = Zs[b * PZ + 24 + uu] + Bs[24 + uu];
                    const float fg = sigm(zf);
                    const float ig = sigm(zi);
                    const float ct = tanhf(zc);
                    const float og = sigm(zo);
                    const float cc = fg * creg[u] + ig * ct;
                    creg[u] = cc;
                    Hs[b * 8 + uu] = og * tanhf(cc);
                }
            }
            __syncthreads();

            // coalesced global h writes (tf32-rounded on the GEMM path)
#pragma unroll
            for (int i = 0; i < 2; ++i) {
                const int idx = tid + i * NTHR;         // 0..511
                const int b = idx >> 2, j = (idx & 3) * 2;
                const float h0v = Hs[b * 8 + j];
                const float h1v = Hs[b * 8 + j + 1];
                const float2 hv = make_float2(f2tf_f(h0v), f2tf_f(h1v));
                if (is0) {
                    *(float2*)&g_A0[nb][b][EDIM + u0 + j] = hv;
                    *(float2*)&g_A1[nb][b][u0 + j]        = hv;
                } else {
                    *(float2*)&g_A1[nb][b][HDIM + u0 + j] = hv;
                    *(float2*)&g_h1f[b][u0 + j]           = make_float2(h0v, h1v);
                }
            }
        }
        gbar();
    }

    // ---------------- epilogue FC: out[b][j] = h1[b] . fcw[j] + fcb[j] ----------------
    if (cta == 0 && tid < BATCH) {
        const int b = tid;
        float s0 = 0.0f, s1 = 0.0f;
        for (int u = 0; u < HDIM; ++u) {
            const float h = g_h1f[b][u];
            s0 += h * fcw[u];
            s1 += h * fcw[HDIM + u];
        }
        out[b * 2 + 0] = s0 + fcb[0];
        out[b * 2 + 1] = s1 + fcb[1];
    }
}

extern "C" void kernel_launch(void* const* d_in, const int* in_sizes, int n_in,
                              void* d_out, int out_size) {
    (void)in_sizes; (void)n_in; (void)out_size;
    cudaFuncSetAttribute(hybrid_qlstm_kernel,
                         cudaFuncAttributeMaxDynamicSharedMemorySize, SMEM_BYTES);
    hybrid_qlstm_kernel<<<NCTA, NTHR, SMEM_BYTES>>>(
        (const int*)d_in[0],  (const float*)d_in[1], (const float*)d_in[2],
        (const float*)d_in[3], (const float*)d_in[4], (const float*)d_in[5],
        (const float*)d_in[6], (const float*)d_in[7], (const float*)d_in[8],
        (const float*)d_in[9], (float*)d_out);
}